// round 2
// baseline (speedup 1.0000x reference)
#include <cuda_runtime.h>
#include <cstdint>

#define NB 32
#define ND 256
#define NT 2048
#define NL 8
#define NK 1024
#define NVEC (NB*NT)                 // 65536 vectors
#define NOUT (NB*ND*NT)              // 16777216 floats (main output)
#define NIDX (NB*NL*NT)              // 524288 index slots

#define TM 128                       // rows (vectors) per block
#define TN 128                       // codes per tile
#define BK 8                         // d-chunk per smem B tile

// Scratch (static device allocations are the sanctioned workaround)
__device__ float g_res[(size_t)NVEC * ND];     // 64 MB residual, (N, D) row-major
__device__ float g_norms[NL * NK];             // |W_k|^2 per layer

// SMEM layout for vq_layer_kernel (floats):
//  As    : TM*ND      = 32768
//  Bs    : BK*TN      = 1024
//  Ns    : NK         = 1024
//  An    : TM         = 128   (|r|^2 per row, XLA-order)
//  Rv    : TM*16      = 2048
//  Ri    : TM*16      = 2048 (ints)
//  RowIdx: TM         = 128  (ints)
#define SMEM_FLOATS (TM*ND + BK*TN + NK + TM + TM*16)
#define SMEM_BYTES  (SMEM_FLOATS*4 + TM*16*4 + TM*4)

// ---------------------------------------------------------------- packed fp32x2
__device__ __forceinline__ unsigned long long pack2(float a, float b) {
    unsigned long long r;
    asm("mov.b64 %0, {%1, %2};" : "=l"(r) : "f"(a), "f"(b));
    return r;
}
__device__ __forceinline__ unsigned long long ffma2(unsigned long long a,
                                                    unsigned long long b,
                                                    unsigned long long c) {
    unsigned long long d;
    asm("fma.rn.f32x2 %0, %1, %2, %3;" : "=l"(d) : "l"(a), "l"(b), "l"(c));
    return d;
}
__device__ __forceinline__ float2 unpack2(unsigned long long v) {
    float2 r;
    asm("mov.b64 {%0, %1}, %2;" : "=f"(r.x), "=f"(r.y) : "l"(v));
    return r;
}

// XLA-style warp row-reduce: partials = sum_i v[lane+32i]^2 (mul then add,
// NO fma — XLA does not contract), then binary tree identical to
// shfl_down(16,8,4,2,1) at lane 0.
__device__ __forceinline__ float warp_sumsq_x32(const float* __restrict__ p, int lane) {
    float s = 0.f;
    #pragma unroll
    for (int i = 0; i < ND / 32; i++) {
        float v = p[lane + 32 * i];
        s = __fadd_rn(s, __fmul_rn(v, v));
    }
    #pragma unroll
    for (int o = 16; o; o >>= 1)
        s = __fadd_rn(s, __shfl_xor_sync(0xffffffffu, s, o));
    return s;
}

// ---------------------------------------------------------------- codebook norms
__global__ void norms_kernel(const float* __restrict__ cb) {
    int w    = (blockIdx.x * blockDim.x + threadIdx.x) >> 5;   // one warp per (l,k)
    int lane = threadIdx.x & 31;
    if (w >= NL * NK) return;
    float s = warp_sumsq_x32(cb + (size_t)w * ND, lane);
    if (lane == 0) g_norms[w] = s;
}

// ---------------------------------------------------------------- x (B,D,T) -> res (N,D)
__global__ void tin_kernel(const float* __restrict__ x) {
    __shared__ float tile[32][33];
    int b  = blockIdx.z;
    int d0 = blockIdx.y * 32, t0 = blockIdx.x * 32;
    int tx = threadIdx.x, ty = threadIdx.y;          // (32, 8)
    #pragma unroll
    for (int i = 0; i < 32; i += 8)
        tile[ty + i][tx] = x[((size_t)b * ND + d0 + ty + i) * NT + t0 + tx];
    __syncthreads();
    #pragma unroll
    for (int i = 0; i < 32; i += 8)
        g_res[((size_t)(b * NT + t0 + ty + i)) * ND + d0 + tx] = tile[tx][ty + i];
}

// ---------------------------------------------------------------- out = x - res (transposed back)
__global__ void tout_kernel(const float* __restrict__ x, float* __restrict__ out) {
    __shared__ float tile[32][33];
    int b  = blockIdx.z;
    int d0 = blockIdx.y * 32, t0 = blockIdx.x * 32;
    int tx = threadIdx.x, ty = threadIdx.y;
    #pragma unroll
    for (int i = 0; i < 32; i += 8)
        tile[ty + i][tx] = g_res[((size_t)(b * NT + t0 + ty + i)) * ND + d0 + tx];
    __syncthreads();
    size_t base = (size_t)b * ND * NT;
    #pragma unroll
    for (int i = 0; i < 32; i += 8) {
        size_t o = base + (size_t)(d0 + ty + i) * NT + t0 + tx;
        out[o] = __fsub_rn(x[o], tile[tx][ty + i]);
    }
}

// ---------------------------------------------------------------- one RVQ layer
__global__ void __launch_bounds__(256, 1) vq_layer_kernel(
    const float* __restrict__ codebooks,
    float* __restrict__ idx_out,     // base of index region (may be unused)
    int l, int write_idx)
{
    extern __shared__ float sm[];
    float* As     = sm;                       // [TM][ND]
    float* Bs     = As + TM * ND;             // [BK][TN]
    float* Ns     = Bs + BK * TN;             // [NK]
    float* An     = Ns + NK;                  // [TM]
    float* Rv     = An + TM;                  // [TM][16]
    int*   Ri     = (int*)(Rv + TM * 16);     // [TM][16]
    int*   RowIdx = Ri + TM * 16;             // [TM]

    const float* W   = codebooks + (size_t)l * NK * ND;
    const int  row0  = blockIdx.x * TM;
    const int  tid   = threadIdx.x;
    const int  lane  = tid & 31;
    const int  warp  = tid >> 5;

    // Load residual tile (128x256 fp32) fully into SMEM; stays resident all K.
    {
        float4*       d4 = (float4*)As;
        const float4* s4 = (const float4*)(g_res + (size_t)row0 * ND);
        #pragma unroll
        for (int i = 0; i < (TM * ND / 4) / 256; i++) d4[tid + i * 256] = s4[tid + i * 256];
    }
    for (int i = tid; i < NK; i += 256) Ns[i] = g_norms[l * NK + i];
    __syncthreads();

    // |r|^2 per row, XLA reduce order (term matters: ref dist = (A - 2B) + C).
    #pragma unroll
    for (int rr = 0; rr < TM / 8; rr++) {
        int r = warp + rr * 8;
        float s = warp_sumsq_x32(&As[r * ND], lane);
        if (lane == 0) An[r] = s;
    }
    __syncthreads();

    const int tx = tid & 15, ty = tid >> 4;   // 16x16 thread grid, 8x8 microtile
    float rowA[8];
    #pragma unroll
    for (int i = 0; i < 8; i++) rowA[i] = An[ty * 8 + i];

    float bestv[8]; int besti[8];
    #pragma unroll
    for (int i = 0; i < 8; i++) { bestv[i] = 3.4e38f; besti[i] = 0; }

    const int    bc    = tid >> 1;            // B-load: column 0..127
    const int    bh    = (tid & 1) * 4;       // half of the 8-wide d chunk
    const float* wsrc  = W + (size_t)bc * ND + bh;

    for (int ntile = 0; ntile < NK / TN; ntile++) {
        unsigned long long acc[8][4];
        #pragma unroll
        for (int i = 0; i < 8; i++)
            #pragma unroll
            for (int j = 0; j < 4; j++) acc[i][j] = 0ull;

        const float* wt = wsrc + (size_t)ntile * TN * ND;

        for (int dk0 = 0; dk0 < ND; dk0 += BK) {
            float4 v = *(const float4*)(wt + dk0);   // prefetch before barrier
            __syncthreads();                         // previous Bs fully consumed
            Bs[(bh + 0) * TN + bc] = v.x;            // store transposed [dk][col]
            Bs[(bh + 1) * TN + bc] = v.y;
            Bs[(bh + 2) * TN + bc] = v.z;
            Bs[(bh + 3) * TN + bc] = v.w;
            __syncthreads();

            #pragma unroll
            for (int g = 0; g < 2; g++) {
                float4 av[8];
                #pragma unroll
                for (int i = 0; i < 8; i++)
                    av[i] = *(const float4*)&As[(ty * 8 + i) * ND + dk0 + g * 4];
                #pragma unroll
                for (int dd = 0; dd < 4; dd++) {
                    const float* bp = &Bs[(g * 4 + dd) * TN + tx * 8];
                    unsigned long long b0 = *(const unsigned long long*)(bp + 0);
                    unsigned long long b1 = *(const unsigned long long*)(bp + 2);
                    unsigned long long b2 = *(const unsigned long long*)(bp + 4);
                    unsigned long long b3 = *(const unsigned long long*)(bp + 6);
                    #pragma unroll
                    for (int i = 0; i < 8; i++) {
                        float a = (dd == 0) ? av[i].x : (dd == 1) ? av[i].y
                                 : (dd == 2) ? av[i].z : av[i].w;
                        unsigned long long a2 = pack2(a, a);
                        acc[i][0] = ffma2(a2, b0, acc[i][0]);
                        acc[i][1] = ffma2(a2, b1, acc[i][1]);
                        acc[i][2] = ffma2(a2, b2, acc[i][2]);
                        acc[i][3] = ffma2(a2, b3, acc[i][3]);
                    }
                }
            }
        }

        // Fold this code tile into the running argmin.
        // dist replicates ref's rounding: rn(rn(A - 2B) + C).
        // Scan order is ascending code index everywhere -> strict '<' keeps the
        // FIRST minimum, matching jnp.argmin.
        #pragma unroll
        for (int i = 0; i < 8; i++) {
            #pragma unroll
            for (int j = 0; j < 4; j++) {
                float2 p  = unpack2(acc[i][j]);
                int   col = ntile * TN + tx * 8 + 2 * j;
                float d0 = __fadd_rn(__fsub_rn(rowA[i], __fmul_rn(2.f, p.x)), Ns[col]);
                float d1 = __fadd_rn(__fsub_rn(rowA[i], __fmul_rn(2.f, p.y)), Ns[col + 1]);
                if (d0 < bestv[i]) { bestv[i] = d0; besti[i] = col; }
                if (d1 < bestv[i]) { bestv[i] = d1; besti[i] = col + 1; }
            }
        }
    }

    // Cross-thread per-row argmin reduce (16 partials per row).
    __syncthreads();
    #pragma unroll
    for (int i = 0; i < 8; i++) {
        int r = ty * 8 + i;
        Rv[r * 16 + tx] = bestv[i];
        Ri[r * 16 + tx] = besti[i];
    }
    __syncthreads();
    if (tid < TM) {
        float bv = Rv[tid * 16]; int bi = Ri[tid * 16];
        #pragma unroll
        for (int t = 1; t < 16; t++) {
            float v = Rv[tid * 16 + t]; int ii = Ri[tid * 16 + t];
            if (v < bv || (v == bv && ii < bi)) { bv = v; bi = ii; }
        }
        RowIdx[tid] = bi;
        if (write_idx) {
            int n = row0 + tid;
            int b = n >> 11;           // T = 2048
            int t = n & (NT - 1);
            idx_out[(size_t)b * NL * NT + (size_t)l * NT + t] = (float)bi;
        }
    }
    __syncthreads();

    // residual -= gathered code; write back for next layer.
    {
        float4*       gout = (float4*)(g_res + (size_t)row0 * ND);
        const float4* As4  = (const float4*)As;
        #pragma unroll
        for (int it = 0; it < (TM * (ND / 4)) / 256; it++) {
            int e   = tid + it * 256;
            int row = e >> 6;          // 64 float4 per row
            int d4  = e & 63;
            float4 w4 = *(const float4*)(W + (size_t)RowIdx[row] * ND + 4 * d4);
            float4 a4 = As4[e];
            gout[e] = make_float4(__fsub_rn(a4.x, w4.x), __fsub_rn(a4.y, w4.y),
                                  __fsub_rn(a4.z, w4.z), __fsub_rn(a4.w, w4.w));
        }
    }
}

// ---------------------------------------------------------------- launch
extern "C" void kernel_launch(void* const* d_in, const int* in_sizes, int n_in,
                              void* d_out, int out_size) {
    const float* x  = (const float*)d_in[0];
    const float* cb = (const float*)d_in[1];
    // robustness: swap if metadata order differs
    if (n_in >= 2 && in_sizes[0] == NL * NK * ND && in_sizes[1] == NB * ND * NT) {
        const float* t = x; x = cb; cb = t;
    }
    float* out = (float*)d_out;
    int write_idx = (out_size >= NOUT + NIDX) ? 1 : 0;

    cudaFuncSetAttribute(vq_layer_kernel,
                         cudaFuncAttributeMaxDynamicSharedMemorySize, SMEM_BYTES);

    norms_kernel<<<(NL * NK * 32 + 255) / 256, 256>>>(cb);

    dim3 tb(32, 8);
    tin_kernel<<<dim3(NT / 32, ND / 32, NB), tb>>>(x);

    for (int l = 0; l < NL; l++)
        vq_layer_kernel<<<NVEC / TM, 256, SMEM_BYTES>>>(cb, out + NOUT, l, write_idx);

    tout_kernel<<<dim3(NT / 32, ND / 32, NB), tb>>>(x, out);
}

// round 3
// speedup vs baseline: 1.1937x; 1.1937x over previous
#include <cuda_runtime.h>
#include <cstdint>

#define NB 32
#define ND 256
#define NT 2048
#define NL 8
#define NK 1024
#define NVEC (NB*NT)                 // 65536 vectors
#define NOUT (NB*ND*NT)              // 16777216 floats (main output)
#define NIDX (NB*NL*NT)              // 524288 index slots

#define TM 128                       // rows (vectors) per block
#define TN 128                       // codes per tile
#define SK 16                        // d-span per staged B superchunk
#define NTHREADS 512
#define NTILES (NK/TN)               // 8
#define NSC (ND/SK)                  // 16 superchunks per ntile

// Scratch (static device allocations are the sanctioned workaround)
__device__ float g_res[(size_t)NVEC * ND];     // 64 MB residual, (N, D) row-major
__device__ float g_norms[NL * NK];             // |W_k|^2 per layer

// SMEM layout (floats):
//  As    : TM*ND      = 32768
//  Bs    : 2*SK*TN    = 4096   (double-buffered)
//  Ns    : NK         = 1024
//  An    : TM         = 128
//  Rv    : TM*16      = 2048
//  Ri    : TM*16      = 2048 (ints)
//  RowIdx: TM         = 128  (ints)
#define SMEM_FLOATS (TM*ND + 2*SK*TN + NK + TM + TM*16)
#define SMEM_BYTES  (SMEM_FLOATS*4 + TM*16*4 + TM*4)

typedef unsigned long long ull;

// ---------------------------------------------------------------- packed fp32x2
__device__ __forceinline__ ull pack2(float a, float b) {
    ull r;
    asm("mov.b64 %0, {%1, %2};" : "=l"(r) : "f"(a), "f"(b));
    return r;
}
__device__ __forceinline__ ull ffma2(ull a, ull b, ull c) {
    ull d;
    asm("fma.rn.f32x2 %0, %1, %2, %3;" : "=l"(d) : "l"(a), "l"(b), "l"(c));
    return d;
}
__device__ __forceinline__ float2 unpack2(ull v) {
    float2 r;
    asm("mov.b64 {%0, %1}, %2;" : "=f"(r.x), "=f"(r.y) : "l"(v));
    return r;
}

// XLA-style warp row-reduce: partials = sum_i v[lane+32i]^2 (mul then add,
// NO fma — XLA does not contract), then xor-butterfly tree (== shfl_down tree
// at lane 0).
__device__ __forceinline__ float warp_sumsq_x32(const float* __restrict__ p, int lane) {
    float s = 0.f;
    #pragma unroll
    for (int i = 0; i < ND / 32; i++) {
        float v = p[lane + 32 * i];
        s = __fadd_rn(s, __fmul_rn(v, v));
    }
    #pragma unroll
    for (int o = 16; o; o >>= 1)
        s = __fadd_rn(s, __shfl_xor_sync(0xffffffffu, s, o));
    return s;
}

// ---------------------------------------------------------------- codebook norms
__global__ void norms_kernel(const float* __restrict__ cb) {
    int w    = (blockIdx.x * blockDim.x + threadIdx.x) >> 5;   // one warp per (l,k)
    int lane = threadIdx.x & 31;
    if (w >= NL * NK) return;
    float s = warp_sumsq_x32(cb + (size_t)w * ND, lane);
    if (lane == 0) g_norms[w] = s;
}

// ---------------------------------------------------------------- x (B,D,T) -> res (N,D)
__global__ void tin_kernel(const float* __restrict__ x) {
    __shared__ float tile[32][33];
    int b  = blockIdx.z;
    int d0 = blockIdx.y * 32, t0 = blockIdx.x * 32;
    int tx = threadIdx.x, ty = threadIdx.y;          // (32, 8)
    #pragma unroll
    for (int i = 0; i < 32; i += 8)
        tile[ty + i][tx] = x[((size_t)b * ND + d0 + ty + i) * NT + t0 + tx];
    __syncthreads();
    #pragma unroll
    for (int i = 0; i < 32; i += 8)
        g_res[((size_t)(b * NT + t0 + ty + i)) * ND + d0 + tx] = tile[tx][ty + i];
}

// ---------------------------------------------------------------- out = x - res (transposed back)
__global__ void tout_kernel(const float* __restrict__ x, float* __restrict__ out) {
    __shared__ float tile[32][33];
    int b  = blockIdx.z;
    int d0 = blockIdx.y * 32, t0 = blockIdx.x * 32;
    int tx = threadIdx.x, ty = threadIdx.y;
    #pragma unroll
    for (int i = 0; i < 32; i += 8)
        tile[ty + i][tx] = g_res[((size_t)(b * NT + t0 + ty + i)) * ND + d0 + tx];
    __syncthreads();
    size_t base = (size_t)b * ND * NT;
    #pragma unroll
    for (int i = 0; i < 32; i += 8) {
        size_t o = base + (size_t)(d0 + ty + i) * NT + t0 + tx;
        out[o] = __fsub_rn(x[o], tile[tx][ty + i]);
    }
}

// ---------------------------------------------------------------- one RVQ layer
__global__ void __launch_bounds__(NTHREADS, 1) vq_layer_kernel(
    const float* __restrict__ codebooks,
    float* __restrict__ idx_out,
    int l, int write_idx)
{
    extern __shared__ float sm[];
    float* As     = sm;                         // [TM][ND]
    float* Bs     = As + TM * ND;               // [2][SK][TN]
    float* Ns     = Bs + 2 * SK * TN;           // [NK]
    float* An     = Ns + NK;                    // [TM]
    float* Rv     = An + TM;                    // [TM][16]
    int*   Ri     = (int*)(Rv + TM * 16);       // [TM][16]
    int*   RowIdx = Ri + TM * 16;               // [TM]

    const float* W   = codebooks + (size_t)l * NK * ND;
    const int  row0  = blockIdx.x * TM;
    const int  tid   = threadIdx.x;
    const int  lane  = tid & 31;
    const int  warp  = tid >> 5;

    // Load residual tile (128x256 fp32) into SMEM; resident for the full K loop.
    {
        float4*       d4 = (float4*)As;
        const float4* s4 = (const float4*)(g_res + (size_t)row0 * ND);
        #pragma unroll
        for (int i = 0; i < (TM * ND / 4) / NTHREADS; i++)
            d4[tid + i * NTHREADS] = s4[tid + i * NTHREADS];
    }
    for (int i = tid; i < NK; i += NTHREADS) Ns[i] = g_norms[l * NK + i];
    __syncthreads();

    // |r|^2 per row, XLA reduce order (ref dist = (A - 2B) + C).
    #pragma unroll
    for (int rr = 0; rr < TM / 16; rr++) {
        int r = rr * 16 + warp;
        float s = warp_sumsq_x32(&As[r * ND], lane);
        if (lane == 0) An[r] = s;
    }
    __syncthreads();

    // Compute mapping: tx owns 8 strided cols (2tx + 32j), ty owns 4 rows.
    const int tx = tid & 15, ty = tid >> 4;
    float rowA[4];
    #pragma unroll
    for (int i = 0; i < 4; i++) rowA[i] = An[ty * 4 + i];

    float bestv[4]; int besti[4];
    #pragma unroll
    for (int i = 0; i < 4; i++) { bestv[i] = 3.4e38f; besti[i] = 0; }

    // B staging mapping: thread loads 4 consecutive d's of one code row.
    const int    bcol = tid & 127;
    const int    bh   = ((tid >> 7) & 3) * 4;
    const float* wb   = W + (size_t)bcol * ND + bh;

    float4 v_cur = *(const float4*)wb;          // cc = 0 (ntile 0, sk0 0)
    int p = 0;

    for (int ntile = 0; ntile < NTILES; ntile++) {
        ull acc[4][4];
        #pragma unroll
        for (int i = 0; i < 4; i++)
            #pragma unroll
            for (int j = 0; j < 4; j++) acc[i][j] = 0ull;

        for (int sc = 0; sc < NSC; sc++) {
            const int cc = ntile * NSC + sc;
            const int nn = (cc < NTILES * NSC - 1) ? cc + 1 : cc;
            float4 v_next = *(const float4*)(wb + (size_t)(nn >> 4) * TN * ND
                                                + (nn & 15) * SK);

            float* bd = Bs + p * (SK * TN);
            bd[(bh + 0) * TN + bcol] = v_cur.x;
            bd[(bh + 1) * TN + bcol] = v_cur.y;
            bd[(bh + 2) * TN + bcol] = v_cur.z;
            bd[(bh + 3) * TN + bcol] = v_cur.w;
            __syncthreads();                     // single barrier per superchunk

            const int sk0 = sc * SK;
            #pragma unroll
            for (int g = 0; g < SK / 4; g++) {
                float4 av[4];
                #pragma unroll
                for (int i = 0; i < 4; i++)
                    av[i] = *(const float4*)&As[(ty * 4 + i) * ND + sk0 + g * 4];
                #pragma unroll
                for (int dd = 0; dd < 4; dd++) {
                    const float* bp = bd + (g * 4 + dd) * TN + 2 * tx;
                    ull b0 = *(const ull*)(bp + 0);
                    ull b1 = *(const ull*)(bp + 32);
                    ull b2 = *(const ull*)(bp + 64);
                    ull b3 = *(const ull*)(bp + 96);
                    #pragma unroll
                    for (int i = 0; i < 4; i++) {
                        float a = (dd == 0) ? av[i].x : (dd == 1) ? av[i].y
                                 : (dd == 2) ? av[i].z : av[i].w;
                        ull a2 = pack2(a, a);
                        acc[i][0] = ffma2(a2, b0, acc[i][0]);
                        acc[i][1] = ffma2(a2, b1, acc[i][1]);
                        acc[i][2] = ffma2(a2, b2, acc[i][2]);
                        acc[i][3] = ffma2(a2, b3, acc[i][3]);
                    }
                }
            }
            p ^= 1;
            v_cur = v_next;
        }

        // Fold this code tile into the running argmin.
        // dist replicates ref rounding: rn(rn(A - 2B) + C).
        // Within-thread scan is ascending col -> strict '<' keeps FIRST min.
        #pragma unroll
        for (int i = 0; i < 4; i++) {
            #pragma unroll
            for (int j = 0; j < 4; j++) {
                float2 pq = unpack2(acc[i][j]);
                int   col = ntile * TN + 32 * j + 2 * tx;
                float d0 = __fadd_rn(__fsub_rn(rowA[i], __fmul_rn(2.f, pq.x)), Ns[col]);
                float d1 = __fadd_rn(__fsub_rn(rowA[i], __fmul_rn(2.f, pq.y)), Ns[col + 1]);
                if (d0 < bestv[i]) { bestv[i] = d0; besti[i] = col; }
                if (d1 < bestv[i]) { bestv[i] = d1; besti[i] = col + 1; }
            }
        }
    }

    // Cross-thread per-row argmin reduce (16 partials per row), index tie-break.
    __syncthreads();
    #pragma unroll
    for (int i = 0; i < 4; i++) {
        int r = ty * 4 + i;
        Rv[r * 16 + tx] = bestv[i];
        Ri[r * 16 + tx] = besti[i];
    }
    __syncthreads();
    if (tid < TM) {
        float bv = Rv[tid * 16]; int bi = Ri[tid * 16];
        #pragma unroll
        for (int t = 1; t < 16; t++) {
            float v = Rv[tid * 16 + t]; int ii = Ri[tid * 16 + t];
            if (v < bv || (v == bv && ii < bi)) { bv = v; bi = ii; }
        }
        RowIdx[tid] = bi;
        if (write_idx) {
            int n = row0 + tid;
            int b = n >> 11;           // T = 2048
            int t = n & (NT - 1);
            idx_out[(size_t)b * NL * NT + (size_t)l * NT + t] = (float)bi;
        }
    }
    __syncthreads();

    // residual -= gathered code; write back for next layer.
    {
        float4*       gout = (float4*)(g_res + (size_t)row0 * ND);
        const float4* As4  = (const float4*)As;
        #pragma unroll
        for (int it = 0; it < (TM * (ND / 4)) / NTHREADS; it++) {
            int e   = tid + it * NTHREADS;
            int row = e >> 6;          // 64 float4 per row
            int d4  = e & 63;
            float4 w4 = *(const float4*)(W + (size_t)RowIdx[row] * ND + 4 * d4);
            float4 a4 = As4[e];
            gout[e] = make_float4(__fsub_rn(a4.x, w4.x), __fsub_rn(a4.y, w4.y),
                                  __fsub_rn(a4.z, w4.z), __fsub_rn(a4.w, w4.w));
        }
    }
}

// ---------------------------------------------------------------- launch
extern "C" void kernel_launch(void* const* d_in, const int* in_sizes, int n_in,
                              void* d_out, int out_size) {
    const float* x  = (const float*)d_in[0];
    const float* cb = (const float*)d_in[1];
    if (n_in >= 2 && in_sizes[0] == NL * NK * ND && in_sizes[1] == NB * ND * NT) {
        const float* t = x; x = cb; cb = t;
    }
    float* out = (float*)d_out;
    int write_idx = (out_size >= NOUT + NIDX) ? 1 : 0;

    cudaFuncSetAttribute(vq_layer_kernel,
                         cudaFuncAttributeMaxDynamicSharedMemorySize, SMEM_BYTES);

    norms_kernel<<<(NL * NK * 32 + 255) / 256, 256>>>(cb);

    dim3 tb(32, 8);
    tin_kernel<<<dim3(NT / 32, ND / 32, NB), tb>>>(x);

    for (int l = 0; l < NL; l++)
        vq_layer_kernel<<<NVEC / TM, NTHREADS, SMEM_BYTES>>>(cb, out + NOUT, l, write_idx);

    tout_kernel<<<dim3(NT / 32, ND / 32, NB), tb>>>(x, out);
}

// round 4
// speedup vs baseline: 1.3953x; 1.1690x over previous
#include <cuda_runtime.h>
#include <cstdint>

#define NB 32
#define ND 256
#define NT 2048
#define NL 8
#define NK 1024
#define NVEC (NB*NT)                 // 65536 vectors
#define NOUT (NB*ND*NT)              // 16777216 floats (main output)
#define NIDX (NB*NL*NT)              // 524288 index slots

#define TM 128                       // rows (vectors) per block
#define TN 256                       // codes per tile
#define SK 16                        // d-span per staged B superchunk
#define NTHREADS 512
#define NTILES (NK/TN)               // 4
#define NSC (ND/SK)                  // 16 superchunks per ntile

// Scratch (static device allocations are the sanctioned workaround)
__device__ float g_res[(size_t)NVEC * ND];     // 64 MB residual, (N, D) row-major
__device__ float g_norms[NL * NK];             // |W_k|^2 per layer

// SMEM layout (floats):
//  As    : TM*ND     = 32768
//  Bs    : 2*SK*TN   = 8192   (double-buffered)
//  Ns    : NK        = 1024
//  An    : TM        = 128
//  RowIdx: TM        = 128  (ints)
#define SMEM_FLOATS (TM*ND + 2*SK*TN + NK + TM)
#define SMEM_BYTES  (SMEM_FLOATS*4 + TM*4)

typedef unsigned long long ull;

// ---------------------------------------------------------------- packed fp32x2
__device__ __forceinline__ ull pack2(float a, float b) {
    ull r;
    asm("mov.b64 %0, {%1, %2};" : "=l"(r) : "f"(a), "f"(b));
    return r;
}
__device__ __forceinline__ ull ffma2(ull a, ull b, ull c) {
    ull d;
    asm("fma.rn.f32x2 %0, %1, %2, %3;" : "=l"(d) : "l"(a), "l"(b), "l"(c));
    return d;
}
__device__ __forceinline__ float2 unpack2(ull v) {
    float2 r;
    asm("mov.b64 {%0, %1}, %2;" : "=f"(r.x), "=f"(r.y) : "l"(v));
    return r;
}

// XLA-style warp row-reduce: partials = sum_i v[lane+32i]^2 (mul then add,
// NO fma — XLA does not contract), then xor-butterfly tree.
__device__ __forceinline__ float warp_sumsq_x32(const float* __restrict__ p, int lane) {
    float s = 0.f;
    #pragma unroll
    for (int i = 0; i < ND / 32; i++) {
        float v = p[lane + 32 * i];
        s = __fadd_rn(s, __fmul_rn(v, v));
    }
    #pragma unroll
    for (int o = 16; o; o >>= 1)
        s = __fadd_rn(s, __shfl_xor_sync(0xffffffffu, s, o));
    return s;
}

// ---------------------------------------------------------------- codebook norms
__global__ void norms_kernel(const float* __restrict__ cb) {
    int w    = (blockIdx.x * blockDim.x + threadIdx.x) >> 5;   // one warp per (l,k)
    int lane = threadIdx.x & 31;
    if (w >= NL * NK) return;
    float s = warp_sumsq_x32(cb + (size_t)w * ND, lane);
    if (lane == 0) g_norms[w] = s;
}

// ---------------------------------------------------------------- x (B,D,T) -> res (N,D)
__global__ void tin_kernel(const float* __restrict__ x) {
    __shared__ float tile[32][33];
    int b  = blockIdx.z;
    int d0 = blockIdx.y * 32, t0 = blockIdx.x * 32;
    int tx = threadIdx.x, ty = threadIdx.y;          // (32, 8)
    #pragma unroll
    for (int i = 0; i < 32; i += 8)
        tile[ty + i][tx] = x[((size_t)b * ND + d0 + ty + i) * NT + t0 + tx];
    __syncthreads();
    #pragma unroll
    for (int i = 0; i < 32; i += 8)
        g_res[((size_t)(b * NT + t0 + ty + i)) * ND + d0 + tx] = tile[tx][ty + i];
}

// ---------------------------------------------------------------- out = x - res (transposed back)
__global__ void tout_kernel(const float* __restrict__ x, float* __restrict__ out) {
    __shared__ float tile[32][33];
    int b  = blockIdx.z;
    int d0 = blockIdx.y * 32, t0 = blockIdx.x * 32;
    int tx = threadIdx.x, ty = threadIdx.y;
    #pragma unroll
    for (int i = 0; i < 32; i += 8)
        tile[ty + i][tx] = g_res[((size_t)(b * NT + t0 + ty + i)) * ND + d0 + tx];
    __syncthreads();
    size_t base = (size_t)b * ND * NT;
    #pragma unroll
    for (int i = 0; i < 32; i += 8) {
        size_t o = base + (size_t)(d0 + ty + i) * NT + t0 + tx;
        out[o] = __fsub_rn(x[o], tile[tx][ty + i]);
    }
}

// ---------------------------------------------------------------- one RVQ layer
__global__ void __launch_bounds__(NTHREADS, 1) vq_layer_kernel(
    const float* __restrict__ codebooks,
    float* __restrict__ idx_out,
    int l, int write_idx)
{
    extern __shared__ float sm[];
    float* As     = sm;                         // [TM][ND]
    float* Bs     = As + TM * ND;               // [2][SK][TN]
    float* Ns     = Bs + 2 * SK * TN;           // [NK]
    float* An     = Ns + NK;                    // [TM]
    int*   RowIdx = (int*)(An + TM);            // [TM]

    const float* W   = codebooks + (size_t)l * NK * ND;
    const int  row0  = blockIdx.x * TM;
    const int  tid   = threadIdx.x;
    const int  lane  = tid & 31;
    const int  warp  = tid >> 5;

    // Load residual tile (128x256 fp32) into SMEM; resident for the full K loop.
    {
        float4*       d4 = (float4*)As;
        const float4* s4 = (const float4*)(g_res + (size_t)row0 * ND);
        #pragma unroll
        for (int i = 0; i < (TM * ND / 4) / NTHREADS; i++)
            d4[tid + i * NTHREADS] = s4[tid + i * NTHREADS];
    }
    for (int i = tid; i < NK; i += NTHREADS) Ns[i] = g_norms[l * NK + i];
    __syncthreads();

    // |r|^2 per row, XLA reduce order (ref dist = (A - 2B) + C).
    #pragma unroll
    for (int rr = 0; rr < TM / 16; rr++) {
        int r = rr * 16 + warp;
        float s = warp_sumsq_x32(&As[r * ND], lane);
        if (lane == 0) An[r] = s;
    }
    __syncthreads();

    // Compute mapping: warp (=ty) owns 8 rows; lane (=tx) owns 8 strided cols
    // (2*lane + 64j). All A loads are warp-broadcast; argmin reduce is shfl-only.
    const int tx = lane, ty = warp;
    const float* arow = &As[ty * 8 * ND];

    float bestv[8]; int besti[8];
    #pragma unroll
    for (int i = 0; i < 8; i++) { bestv[i] = 3.4e38f; besti[i] = 0; }

    // B staging mapping: thread loads 8 consecutive d's of one code row.
    const int    bcol = tid & 255;
    const int    bh   = (tid >> 8) * 8;          // 0 or 8
    const float* wb   = W + (size_t)bcol * ND + bh;

    float4 va = *(const float4*)(wb);            // cc = 0
    float4 vb = *(const float4*)(wb + 4);
    int p = 0;

    for (int ntile = 0; ntile < NTILES; ntile++) {
        ull acc[8][4];
        #pragma unroll
        for (int i = 0; i < 8; i++)
            #pragma unroll
            for (int j = 0; j < 4; j++) acc[i][j] = 0ull;

        for (int sc = 0; sc < NSC; sc++) {
            const int cc = ntile * NSC + sc;
            const int nn = (cc < NTILES * NSC - 1) ? cc + 1 : cc;
            const float* wn = wb + (size_t)(nn >> 4) * TN * ND + (nn & 15) * SK;
            float4 na = *(const float4*)(wn);
            float4 nb = *(const float4*)(wn + 4);

            float* bd = Bs + p * (SK * TN);
            bd[(bh + 0) * TN + bcol] = va.x;
            bd[(bh + 1) * TN + bcol] = va.y;
            bd[(bh + 2) * TN + bcol] = va.z;
            bd[(bh + 3) * TN + bcol] = va.w;
            bd[(bh + 4) * TN + bcol] = vb.x;
            bd[(bh + 5) * TN + bcol] = vb.y;
            bd[(bh + 6) * TN + bcol] = vb.z;
            bd[(bh + 7) * TN + bcol] = vb.w;
            __syncthreads();                     // single barrier per superchunk

            const int sk0 = sc * SK;
            #pragma unroll
            for (int g = 0; g < SK / 2; g++) {   // 2 d's per group
                float2 av[8];
                #pragma unroll
                for (int i = 0; i < 8; i++)
                    av[i] = *(const float2*)&arow[i * ND + sk0 + 2 * g];
                #pragma unroll
                for (int dd = 0; dd < 2; dd++) {
                    const float* bp = bd + (2 * g + dd) * TN + 2 * tx;
                    ull b0 = *(const ull*)(bp + 0);
                    ull b1 = *(const ull*)(bp + 64);
                    ull b2 = *(const ull*)(bp + 128);
                    ull b3 = *(const ull*)(bp + 192);
                    #pragma unroll
                    for (int i = 0; i < 8; i++) {
                        float a = dd ? av[i].y : av[i].x;
                        ull a2 = pack2(a, a);
                        acc[i][0] = ffma2(a2, b0, acc[i][0]);
                        acc[i][1] = ffma2(a2, b1, acc[i][1]);
                        acc[i][2] = ffma2(a2, b2, acc[i][2]);
                        acc[i][3] = ffma2(a2, b3, acc[i][3]);
                    }
                }
            }
            p ^= 1;
            va = na; vb = nb;
        }

        // Fold this code tile into the running argmin.
        // dist replicates ref rounding: rn(rn(A - 2B) + C).
        // Within-thread scan ascending col -> strict '<' keeps FIRST min.
        #pragma unroll
        for (int i = 0; i < 8; i++) {
            float A = An[ty * 8 + i];
            #pragma unroll
            for (int j = 0; j < 4; j++) {
                float2 pq = unpack2(acc[i][j]);
                int   col = ntile * TN + 64 * j + 2 * tx;
                float d0 = __fadd_rn(__fsub_rn(A, __fmul_rn(2.f, pq.x)), Ns[col]);
                float d1 = __fadd_rn(__fsub_rn(A, __fmul_rn(2.f, pq.y)), Ns[col + 1]);
                if (d0 < bestv[i]) { bestv[i] = d0; besti[i] = col; }
                if (d1 < bestv[i]) { bestv[i] = d1; besti[i] = col + 1; }
            }
        }
    }

    // Cross-lane argmin per row (lanes own disjoint col sets; tie -> lower idx).
    #pragma unroll
    for (int i = 0; i < 8; i++) {
        float v = bestv[i]; int ix = besti[i];
        #pragma unroll
        for (int o = 16; o; o >>= 1) {
            float v2 = __shfl_xor_sync(0xffffffffu, v, o);
            int   i2 = __shfl_xor_sync(0xffffffffu, ix, o);
            if (v2 < v || (v2 == v && i2 < ix)) { v = v2; ix = i2; }
        }
        if (lane == 0) {
            int r = ty * 8 + i;
            RowIdx[r] = ix;
            if (write_idx) {
                int n = row0 + r;
                int b = n >> 11;           // T = 2048
                int t = n & (NT - 1);
                idx_out[(size_t)b * NL * NT + (size_t)l * NT + t] = (float)ix;
            }
        }
    }
    __syncthreads();

    // residual -= gathered code; write back for next layer.
    {
        float4*       gout = (float4*)(g_res + (size_t)row0 * ND);
        const float4* As4  = (const float4*)As;
        #pragma unroll
        for (int it = 0; it < (TM * (ND / 4)) / NTHREADS; it++) {
            int e   = tid + it * NTHREADS;
            int row = e >> 6;          // 64 float4 per row
            int d4  = e & 63;
            float4 w4 = *(const float4*)(W + (size_t)RowIdx[row] * ND + 4 * d4);
            float4 a4 = As4[e];
            gout[e] = make_float4(__fsub_rn(a4.x, w4.x), __fsub_rn(a4.y, w4.y),
                                  __fsub_rn(a4.z, w4.z), __fsub_rn(a4.w, w4.w));
        }
    }
}

// ---------------------------------------------------------------- launch
extern "C" void kernel_launch(void* const* d_in, const int* in_sizes, int n_in,
                              void* d_out, int out_size) {
    const float* x  = (const float*)d_in[0];
    const float* cb = (const float*)d_in[1];
    if (n_in >= 2 && in_sizes[0] == NL * NK * ND && in_sizes[1] == NB * ND * NT) {
        const float* t = x; x = cb; cb = t;
    }
    float* out = (float*)d_out;
    int write_idx = (out_size >= NOUT + NIDX) ? 1 : 0;

    cudaFuncSetAttribute(vq_layer_kernel,
                         cudaFuncAttributeMaxDynamicSharedMemorySize, SMEM_BYTES);

    norms_kernel<<<(NL * NK * 32 + 255) / 256, 256>>>(cb);

    dim3 tb(32, 8);
    tin_kernel<<<dim3(NT / 32, ND / 32, NB), tb>>>(x);

    for (int l = 0; l < NL; l++)
        vq_layer_kernel<<<NVEC / TM, NTHREADS, SMEM_BYTES>>>(cb, out + NOUT, l, write_idx);

    tout_kernel<<<dim3(NT / 32, ND / 32, NB), tb>>>(x, out);
}

// round 5
// speedup vs baseline: 1.6464x; 1.1799x over previous
#include <cuda_runtime.h>
#include <cstdint>

#define NB 32
#define ND 256
#define NT 2048
#define NL 8
#define NK 1024
#define NVEC (NB*NT)                 // 65536 vectors
#define NOUT (NB*ND*NT)              // main output floats
#define NIDX (NB*NL*NT)              // index slots

#define TM 128                       // rows per CTA
#define NTHREADS 512
#define ASTRIDE 260                  // padded A row stride (floats)
#define WSTRIDE 132                  // padded staged-W row stride (floats)
#define DC 32                        // d per stage
#define TILEN 128                    // codes per ntile
#define NSTAGES ((NK/TILEN)*(ND/DC)) // 64
#define CAP 80
#define WINDOW 2.0f

// Scratch (static device allocations are the sanctioned workaround)
__device__ float g_res[(size_t)NVEC * ND];     // residual (N, D) row-major
__device__ float g_norms[NL * NK];             // |W_k|^2 per layer

// SMEM floats: As 33280 + Ns 1024 + An 128 = 34432
// SMEM u32  : Ws 2*32*132=8448 + runmin 128 + cnt 128 + RowIdx 128 + cand 10240 = 19072
#define SMEM_BYTES ((33280 + 1024 + 128 + 8448 + 128 + 128 + 128 + (TM*CAP)) * 4)

// ---------------------------------------------------------------- helpers
__device__ __forceinline__ uint32_t f2tf32(float x) {
    uint32_t r; asm("cvt.rna.tf32.f32 %0, %1;" : "=r"(r) : "f"(x)); return r;
}
__device__ __forceinline__ void mma_tf32(float* c, const uint32_t* a,
                                         uint32_t b0, uint32_t b1) {
    asm volatile(
        "mma.sync.aligned.m16n8k8.row.col.f32.tf32.tf32.f32 "
        "{%0,%1,%2,%3}, {%4,%5,%6,%7}, {%8,%9}, {%0,%1,%2,%3};"
        : "+f"(c[0]), "+f"(c[1]), "+f"(c[2]), "+f"(c[3])
        : "r"(a[0]), "r"(a[1]), "r"(a[2]), "r"(a[3]), "r"(b0), "r"(b1));
}

// XLA-style warp row-reduce (mul then add, NO fma), xor-butterfly tree.
__device__ __forceinline__ float warp_sumsq_x32(const float* __restrict__ p, int lane) {
    float s = 0.f;
    #pragma unroll
    for (int i = 0; i < ND / 32; i++) {
        float v = p[lane + 32 * i];
        s = __fadd_rn(s, __fmul_rn(v, v));
    }
    #pragma unroll
    for (int o = 16; o; o >>= 1)
        s = __fadd_rn(s, __shfl_xor_sync(0xffffffffu, s, o));
    return s;
}

// ---------------------------------------------------------------- codebook norms
__global__ void norms_kernel(const float* __restrict__ cb) {
    int w    = (blockIdx.x * blockDim.x + threadIdx.x) >> 5;
    int lane = threadIdx.x & 31;
    if (w >= NL * NK) return;
    float s = warp_sumsq_x32(cb + (size_t)w * ND, lane);
    if (lane == 0) g_norms[w] = s;
}

// ---------------------------------------------------------------- x (B,D,T) -> res (N,D)
__global__ void tin_kernel(const float* __restrict__ x) {
    __shared__ float tile[32][33];
    int b  = blockIdx.z;
    int d0 = blockIdx.y * 32, t0 = blockIdx.x * 32;
    int tx = threadIdx.x, ty = threadIdx.y;          // (32, 8)
    #pragma unroll
    for (int i = 0; i < 32; i += 8)
        tile[ty + i][tx] = x[((size_t)b * ND + d0 + ty + i) * NT + t0 + tx];
    __syncthreads();
    #pragma unroll
    for (int i = 0; i < 32; i += 8)
        g_res[((size_t)(b * NT + t0 + ty + i)) * ND + d0 + tx] = tile[tx][ty + i];
}

// ---------------------------------------------------------------- out = x - res
__global__ void tout_kernel(const float* __restrict__ x, float* __restrict__ out) {
    __shared__ float tile[32][33];
    int b  = blockIdx.z;
    int d0 = blockIdx.y * 32, t0 = blockIdx.x * 32;
    int tx = threadIdx.x, ty = threadIdx.y;
    #pragma unroll
    for (int i = 0; i < 32; i += 8)
        tile[ty + i][tx] = g_res[((size_t)(b * NT + t0 + ty + i)) * ND + d0 + tx];
    __syncthreads();
    size_t base = (size_t)b * ND * NT;
    #pragma unroll
    for (int i = 0; i < 32; i += 8) {
        size_t o = base + (size_t)(d0 + ty + i) * NT + t0 + tx;
        out[o] = __fsub_rn(x[o], tile[tx][ty + i]);
    }
}

// ---------------------------------------------------------------- one RVQ layer
__global__ void __launch_bounds__(NTHREADS, 1) vq_layer_kernel(
    const float* __restrict__ codebooks,
    float* __restrict__ idx_out,
    int l, int write_idx)
{
    extern __shared__ float sm[];
    float*    As     = sm;                              // [TM][ASTRIDE]
    float*    Ns     = As + TM * ASTRIDE;               // [NK]
    float*    An     = Ns + NK;                         // [TM]
    uint32_t* Wsu    = (uint32_t*)(An + TM);            // [2][DC][WSTRIDE] tf32
    uint32_t* runmin = Wsu + 2 * DC * WSTRIDE;          // [TM]
    int*      cnt    = (int*)(runmin + TM);             // [TM]
    int*      RowIdx = cnt + TM;                        // [TM]
    uint32_t* cand   = (uint32_t*)(RowIdx + TM);        // [TM][CAP]

    const float* W  = codebooks + (size_t)l * NK * ND;
    const int row0  = blockIdx.x * TM;
    const int tid   = threadIdx.x;
    const int lane  = tid & 31;
    const int warp  = tid >> 5;
    const int mg    = warp & 3;       // M-group: rows 32*mg .. +32
    const int ng    = warp >> 2;      // N-group: cols 32*ng within ntile

    // ---- load residual tile into padded As ----
    {
        float4*       d4 = (float4*)As;
        const float4* s4 = (const float4*)(g_res + (size_t)row0 * ND);
        #pragma unroll
        for (int it = 0; it < (TM * (ND / 4)) / NTHREADS; it++) {
            int e = tid + it * NTHREADS;
            d4[(e >> 6) * (ASTRIDE / 4) + (e & 63)] = s4[e];
        }
    }
    for (int i = tid; i < NK; i += NTHREADS) Ns[i] = g_norms[l * NK + i];
    if (tid < TM) { cnt[tid] = 0; runmin[tid] = 0x7F7FFFFFu; }
    __syncthreads();

    // ---- |r|^2 per row, XLA reduce order ----
    #pragma unroll
    for (int rr = 0; rr < TM / 16; rr++) {
        int r = rr * 16 + warp;
        float s = warp_sumsq_x32(&As[r * ASTRIDE], lane);
        if (lane == 0) An[r] = s;
    }
    __syncthreads();

    // ---- staged TF32 MMA screen ----
    const int kk = tid >> 2;                 // staging: code 0..127
    const int dd = (tid & 3) * 8;            // staging: 8 d's
    float4 va, vb;
    {
        const float* p0 = W + (size_t)kk * ND + dd;   // stage 0: ntile 0, dchunk 0
        va = *(const float4*)p0; vb = *(const float4*)(p0 + 4);
    }
    int pbuf = 0;
    float accf[2][4][4];

    for (int s = 0; s < NSTAGES; s++) {
        const int ntile = s >> 3, dchunk = s & 7;
        if (dchunk == 0) {
            #pragma unroll
            for (int a = 0; a < 2; a++)
                #pragma unroll
                for (int b = 0; b < 4; b++)
                    #pragma unroll
                    for (int c = 0; c < 4; c++) accf[a][b][c] = 0.f;
        }
        // prefetch next stage
        const int sn = (s + 1 < NSTAGES) ? s + 1 : s;
        const float* np = W + (size_t)((sn >> 3) * TILEN + kk) * ND + (sn & 7) * DC + dd;
        float4 na = *(const float4*)np, nb = *(const float4*)(np + 4);

        // store current stage as tf32 into Ws[d][k]
        uint32_t* wsb = Wsu + pbuf * (DC * WSTRIDE);
        wsb[(dd + 0) * WSTRIDE + kk] = f2tf32(va.x);
        wsb[(dd + 1) * WSTRIDE + kk] = f2tf32(va.y);
        wsb[(dd + 2) * WSTRIDE + kk] = f2tf32(va.z);
        wsb[(dd + 3) * WSTRIDE + kk] = f2tf32(va.w);
        wsb[(dd + 4) * WSTRIDE + kk] = f2tf32(vb.x);
        wsb[(dd + 5) * WSTRIDE + kk] = f2tf32(vb.y);
        wsb[(dd + 6) * WSTRIDE + kk] = f2tf32(vb.z);
        wsb[(dd + 7) * WSTRIDE + kk] = f2tf32(vb.w);
        __syncthreads();

        const int dg = dchunk * DC;
        #pragma unroll
        for (int ks = 0; ks < 4; ks++) {
            const int dk = dg + ks * 8;
            uint32_t af[2][4];
            #pragma unroll
            for (int mt = 0; mt < 2; mt++) {
                const float* ab = As + (32 * mg + 16 * mt + (lane >> 2)) * ASTRIDE
                                     + dk + (lane & 3);
                af[mt][0] = f2tf32(ab[0]);
                af[mt][1] = f2tf32(ab[8 * ASTRIDE]);
                af[mt][2] = f2tf32(ab[4]);
                af[mt][3] = f2tf32(ab[8 * ASTRIDE + 4]);
            }
            const uint32_t* bb = Wsu + pbuf * (DC * WSTRIDE)
                               + (ks * 8 + (lane & 3)) * WSTRIDE
                               + ng * 32 + (lane >> 2);
            #pragma unroll
            for (int ns = 0; ns < 4; ns++) {
                uint32_t b0 = bb[ns * 8];
                uint32_t b1 = bb[ns * 8 + 4 * WSTRIDE];
                mma_tf32(accf[0][ns], af[0], b0, b1);
                mma_tf32(accf[1][ns], af[1], b0, b1);
            }
        }
        pbuf ^= 1; va = na; vb = nb;

        // ---- per-ntile epilogue: screen + candidate push ----
        if (dchunk == 7) {
            #pragma unroll
            for (int mt = 0; mt < 2; mt++) {
                #pragma unroll
                for (int h = 0; h < 2; h++) {
                    int row = 32 * mg + 16 * mt + (lane >> 2) + 8 * h;
                    float A = An[row];
                    float dl[8]; float m = 3.4e38f;
                    #pragma unroll
                    for (int ns = 0; ns < 4; ns++)
                        #pragma unroll
                        for (int c = 0; c < 2; c++) {
                            int col = ntile * TILEN + ng * 32 + ns * 8
                                    + 2 * (lane & 3) + c;
                            float dv = A - 2.f * accf[mt][ns][2 * h + c] + Ns[col];
                            dl[ns * 2 + c] = dv;
                            m = fminf(m, dv);
                        }
                    float m2 = m;
                    m2 = fminf(m2, __shfl_xor_sync(0xffffffffu, m2, 1));
                    m2 = fminf(m2, __shfl_xor_sync(0xffffffffu, m2, 2));
                    float rm  = __uint_as_float(runmin[row]);   // racy read = conservative
                    float thr = fminf(m2, rm) + WINDOW;
                    #pragma unroll
                    for (int e = 0; e < 8; e++) {
                        if (dl[e] <= thr) {
                            int col = ntile * TILEN + ng * 32 + (e >> 1) * 8
                                    + 2 * (lane & 3) + (e & 1);
                            int slot = atomicAdd(&cnt[row], 1);
                            if (slot < CAP)
                                cand[row * CAP + slot] =
                                    (__float_as_uint(fmaxf(dl[e], 0.f)) & 0xFFFFFC00u)
                                    | (uint32_t)col;
                        }
                    }
                    if ((lane & 3) == 0)
                        atomicMin(runmin + row, __float_as_uint(fmaxf(m2, 0.f)));
                }
            }
        }
    }
    __syncthreads();

    // ---- exact rescore of candidates (bit-identical chain to validated path) ----
    if (tid < TM) {
        int row = tid;
        float thrF = __uint_as_float(runmin[row]) + WINDOW;
        int n = cnt[row]; if (n > CAP) n = CAP;
        float bv = 3.4e38f; int bi = 1 << 30;
        const float* ar = As + row * ASTRIDE;
        float A = An[row];
        for (int s = 0; s < n; s++) {
            uint32_t u = cand[row * CAP + s];
            if (__uint_as_float(u & 0xFFFFFC00u) > thrF) continue;
            int col = (int)(u & 1023u);
            const float* wr = W + (size_t)col * ND;
            float acc = 0.f;
            #pragma unroll 8
            for (int d = 0; d < ND; d++) acc = __fmaf_rn(ar[d], wr[d], acc);
            float de = __fadd_rn(__fsub_rn(A, __fmul_rn(2.f, acc)), Ns[col]);
            if (de < bv || (de == bv && col < bi)) { bv = de; bi = col; }
        }
        if (bi >= NK) bi = 0;              // unreachable by construction
        RowIdx[row] = bi;
        if (write_idx) {
            int nn = row0 + row;
            int b = nn >> 11;              // T = 2048
            int t = nn & (NT - 1);
            idx_out[(size_t)b * NL * NT + (size_t)l * NT + t] = (float)bi;
        }
    }
    __syncthreads();

    // ---- residual -= gathered code ----
    {
        float4*       gout = (float4*)(g_res + (size_t)row0 * ND);
        const float4* As4  = (const float4*)As;
        #pragma unroll
        for (int it = 0; it < (TM * (ND / 4)) / NTHREADS; it++) {
            int e   = tid + it * NTHREADS;
            int row = e >> 6;
            int d4  = e & 63;
            float4 w4 = *(const float4*)(W + (size_t)RowIdx[row] * ND + 4 * d4);
            float4 a4 = As4[row * (ASTRIDE / 4) + d4];
            gout[e] = make_float4(__fsub_rn(a4.x, w4.x), __fsub_rn(a4.y, w4.y),
                                  __fsub_rn(a4.z, w4.z), __fsub_rn(a4.w, w4.w));
        }
    }
}

// ---------------------------------------------------------------- launch
extern "C" void kernel_launch(void* const* d_in, const int* in_sizes, int n_in,
                              void* d_out, int out_size) {
    const float* x  = (const float*)d_in[0];
    const float* cb = (const float*)d_in[1];
    if (n_in >= 2 && in_sizes[0] == NL * NK * ND && in_sizes[1] == NB * ND * NT) {
        const float* t = x; x = cb; cb = t;
    }
    float* out = (float*)d_out;
    int write_idx = (out_size >= NOUT + NIDX) ? 1 : 0;

    cudaFuncSetAttribute(vq_layer_kernel,
                         cudaFuncAttributeMaxDynamicSharedMemorySize, SMEM_BYTES);

    norms_kernel<<<(NL * NK * 32 + 255) / 256, 256>>>(cb);

    dim3 tb(32, 8);
    tin_kernel<<<dim3(NT / 32, ND / 32, NB), tb>>>(x);

    for (int l = 0; l < NL; l++)
        vq_layer_kernel<<<NVEC / TM, NTHREADS, SMEM_BYTES>>>(cb, out + NOUT, l, write_idx);

    tout_kernel<<<dim3(NT / 32, ND / 32, NB), tb>>>(x, out);
}

// round 6
// speedup vs baseline: 1.8526x; 1.1252x over previous
#include <cuda_runtime.h>
#include <cstdint>

#define NB 32
#define ND 256
#define NT 2048
#define NL 8
#define NK 1024
#define NVEC (NB*NT)
#define NOUT (NB*ND*NT)
#define NIDX (NB*NL*NT)

#define TM 128                       // rows per CTA
#define NTHREADS 512
#define DC 32                        // d per stage
#define TILEN 128                    // codes per ntile
#define NSTAGES ((NK/TILEN)*(ND/DC)) // 64
#define CAP 80
#define WINDOW 2.0f

// Scratch (static device allocations are the sanctioned workaround)
__device__ float g_res[(size_t)NVEC * ND];     // residual (N, D) row-major
__device__ float g_norms[NL * NK];             // |W_k|^2 per layer

// SMEM words (u32):
//  Atf   : 32768  (A fragments, packed float4-per-thread-frag)
//  Ws    : 2*4096 (staged W tf32, fragment-major, double buffered)
//  Ns    : 1024
//  An    : 128
//  runmin: 128, cnt: 128, RowIdx: 128
//  cand  : TM*CAP = 10240
//  pbv   : 512, pbi : 512  (rescore partials)
#define SMEM_WORDS (32768 + 8192 + 1024 + 128 + 128 + 128 + 128 + TM*CAP + 512 + 512)
#define SMEM_BYTES (SMEM_WORDS * 4)

// ---------------------------------------------------------------- helpers
__device__ __forceinline__ uint32_t f2tf32(float x) {
    uint32_t r; asm("cvt.rna.tf32.f32 %0, %1;" : "=r"(r) : "f"(x)); return r;
}
__device__ __forceinline__ void mma_tf32(float* c, const uint32_t* a,
                                         uint32_t b0, uint32_t b1) {
    asm volatile(
        "mma.sync.aligned.m16n8k8.row.col.f32.tf32.tf32.f32 "
        "{%0,%1,%2,%3}, {%4,%5,%6,%7}, {%8,%9}, {%0,%1,%2,%3};"
        : "+f"(c[0]), "+f"(c[1]), "+f"(c[2]), "+f"(c[3])
        : "r"(a[0]), "r"(a[1]), "r"(a[2]), "r"(a[3]), "r"(b0), "r"(b1));
}

// XLA-style warp row-reduce (mul then add, NO fma), xor-butterfly tree.
__device__ __forceinline__ float warp_sumsq_x32(const float* __restrict__ p, int lane) {
    float s = 0.f;
    #pragma unroll
    for (int i = 0; i < ND / 32; i++) {
        float v = p[lane + 32 * i];
        s = __fadd_rn(s, __fmul_rn(v, v));
    }
    #pragma unroll
    for (int o = 16; o; o >>= 1)
        s = __fadd_rn(s, __shfl_xor_sync(0xffffffffu, s, o));
    return s;
}

// ---------------------------------------------------------------- codebook norms
__global__ void norms_kernel(const float* __restrict__ cb) {
    int w    = (blockIdx.x * blockDim.x + threadIdx.x) >> 5;
    int lane = threadIdx.x & 31;
    if (w >= NL * NK) return;
    float s = warp_sumsq_x32(cb + (size_t)w * ND, lane);
    if (lane == 0) g_norms[w] = s;
}

// ---------------------------------------------------------------- x (B,D,T) -> res (N,D)
__global__ void tin_kernel(const float* __restrict__ x) {
    __shared__ float tile[32][33];
    int b  = blockIdx.z;
    int d0 = blockIdx.y * 32, t0 = blockIdx.x * 32;
    int tx = threadIdx.x, ty = threadIdx.y;          // (32, 8)
    #pragma unroll
    for (int i = 0; i < 32; i += 8)
        tile[ty + i][tx] = x[((size_t)b * ND + d0 + ty + i) * NT + t0 + tx];
    __syncthreads();
    #pragma unroll
    for (int i = 0; i < 32; i += 8)
        g_res[((size_t)(b * NT + t0 + ty + i)) * ND + d0 + tx] = tile[tx][ty + i];
}

// ---------------------------------------------------------------- out = x - res
__global__ void tout_kernel(const float* __restrict__ x, float* __restrict__ out) {
    __shared__ float tile[32][33];
    int b  = blockIdx.z;
    int d0 = blockIdx.y * 32, t0 = blockIdx.x * 32;
    int tx = threadIdx.x, ty = threadIdx.y;
    #pragma unroll
    for (int i = 0; i < 32; i += 8)
        tile[ty + i][tx] = g_res[((size_t)(b * NT + t0 + ty + i)) * ND + d0 + tx];
    __syncthreads();
    size_t base = (size_t)b * ND * NT;
    #pragma unroll
    for (int i = 0; i < 32; i += 8) {
        size_t o = base + (size_t)(d0 + ty + i) * NT + t0 + tx;
        out[o] = __fsub_rn(x[o], tile[tx][ty + i]);
    }
}

// ---------------------------------------------------------------- one RVQ layer
__global__ void __launch_bounds__(NTHREADS, 1) vq_layer_kernel(
    const float* __restrict__ codebooks,
    float* __restrict__ idx_out,
    int l, int write_idx)
{
    extern __shared__ uint32_t smu[];
    uint32_t* Atf    = smu;                           // [8192] uint4 slots
    uint32_t* Wsu    = Atf + 32768;                   // [2][1024] uint4 slots
    float*    Ns     = (float*)(Wsu + 8192);          // [NK]
    float*    An     = Ns + NK;                       // [TM]
    uint32_t* runmin = (uint32_t*)(An + TM);          // [TM]
    int*      cnt    = (int*)(runmin + TM);           // [TM]
    int*      RowIdx = cnt + TM;                      // [TM]
    uint32_t* cand   = (uint32_t*)(RowIdx + TM);      // [TM][CAP]
    float*    pbv    = (float*)(cand + TM * CAP);     // [TM][4]
    int*      pbi    = (int*)(pbv + TM * 4);          // [TM][4]

    uint4* Atf4 = (uint4*)Atf;
    uint4* Ws4  = (uint4*)Wsu;

    const float* W  = codebooks + (size_t)l * NK * ND;
    const int row0  = blockIdx.x * TM;
    const float* gA = g_res + (size_t)row0 * ND;      // this CTA's residual tile
    const int tid   = threadIdx.x;
    const int lane  = tid & 31;
    const int warp  = tid >> 5;
    const int mg    = warp & 3;       // M-group (32 rows)
    const int ng    = warp >> 2;      // N-group (32 cols within ntile)

    for (int i = tid; i < NK; i += NTHREADS) Ns[i] = g_norms[l * NK + i];
    if (tid < TM) { cnt[tid] = 0; runmin[tid] = 0x7F7FFFFFu; }

    // ---- |r|^2 per row, XLA reduce order (from global tile) ----
    #pragma unroll
    for (int rr = 0; rr < TM / 16; rr++) {
        int r = rr * 16 + warp;
        float s = warp_sumsq_x32(&gA[(size_t)r * ND], lane);
        if (lane == 0) An[r] = s;
    }

    // ---- build packed-fragment tf32 A buffer (once per layer) ----
    // slot s: lane=s&31, kq=(s>>5)&31, mt=(s>>10)&1, mgb=(s>>11)&3
    // words: A[row][d], A[row+8][d], A[row][d+4], A[row+8][d+4]
    #pragma unroll
    for (int i = 0; i < 8192 / NTHREADS; i++) {
        int s   = tid + i * NTHREADS;
        int lb  = s & 31, kq = (s >> 5) & 31, mt = (s >> 10) & 1, mgb = (s >> 11) & 3;
        int row = mgb * 32 + mt * 16 + (lb >> 2);
        int d   = kq * 8 + (lb & 3);
        uint4 v;
        v.x = f2tf32(gA[(size_t)row * ND + d]);
        v.y = f2tf32(gA[(size_t)(row + 8) * ND + d]);
        v.z = f2tf32(gA[(size_t)row * ND + d + 4]);
        v.w = f2tf32(gA[(size_t)(row + 8) * ND + d + 4]);
        Atf4[s] = v;
    }
    __syncthreads();

    // ---- staged TF32 MMA screen ----
    // staging ownership: ns/r4 in low tid bits -> conflict-free packed STS
    const int ns_s  = tid & 3;
    const int r4_s  = (tid >> 2) & 7;
    const int ng_s  = (tid >> 5) & 3;
    const int ks2_s = (tid >> 7) & 3;
    const int kk    = ng_s * 32 + ns_s * 8 + r4_s;    // code row within tile
    const int dd    = ks2_s * 8;                      // d offset within stage
    const float* wb = W + (size_t)kk * ND + dd;

    float4 va = *(const float4*)(wb);                 // stage 0
    float4 vb = *(const float4*)(wb + 4);
    int pbuf = 0;
    float accf[2][4][4];

    const int lr = lane >> 2, lc = lane & 3;
    const int r4x_l = lr ^ (lc << 1);

    for (int s = 0; s < NSTAGES; s++) {
        const int ntile = s >> 3, dchunk = s & 7;
        if (dchunk == 0) {
            #pragma unroll
            for (int a = 0; a < 2; a++)
                #pragma unroll
                for (int b = 0; b < 4; b++)
                    #pragma unroll
                    for (int c = 0; c < 4; c++) accf[a][b][c] = 0.f;
        }
        const int sn = (s + 1 < NSTAGES) ? s + 1 : s;
        const float* np = wb + (size_t)(sn >> 3) * TILEN * ND + (sn & 7) * DC;
        float4 na = *(const float4*)np, nb = *(const float4*)(np + 4);

        // packed tf32 store: slot(ks2,c4,h,ng,r4^ (c4<<1)), word = ns
        {
            uint32_t* wsb = Wsu + pbuf * 4096;
            float vq[8] = {va.x, va.y, va.z, va.w, vb.x, vb.y, vb.z, vb.w};
            #pragma unroll
            for (int q = 0; q < 8; q++) {
                int c4 = q & 3, h = q >> 2;
                int slot = (((ks2_s * 4 + c4) * 2 + h) * 4 + ng_s) * 8
                         + (r4_s ^ (c4 << 1));
                wsb[slot * 4 + ns_s] = f2tf32(vq[q]);
            }
        }
        __syncthreads();

        const uint4* wsb4 = Ws4 + pbuf * 1024;
        #pragma unroll
        for (int ks2 = 0; ks2 < 4; ks2++) {
            const int kq = dchunk * 4 + ks2;
            uint4 A0 = Atf4[((mg * 2 + 0) * 32 + kq) * 32 + lane];
            uint4 A1 = Atf4[((mg * 2 + 1) * 32 + kq) * 32 + lane];
            int slot0 = (((ks2 * 4 + lc) * 2 + 0) * 4 + ng) * 8 + r4x_l;
            uint4 B0 = wsb4[slot0];
            uint4 B1 = wsb4[slot0 + 32];          // h=1 -> +4*8 slots
            uint32_t af0[4] = {A0.x, A0.y, A0.z, A0.w};
            uint32_t af1[4] = {A1.x, A1.y, A1.z, A1.w};
            mma_tf32(accf[0][0], af0, B0.x, B1.x);
            mma_tf32(accf[1][0], af1, B0.x, B1.x);
            mma_tf32(accf[0][1], af0, B0.y, B1.y);
            mma_tf32(accf[1][1], af1, B0.y, B1.y);
            mma_tf32(accf[0][2], af0, B0.z, B1.z);
            mma_tf32(accf[1][2], af1, B0.z, B1.z);
            mma_tf32(accf[0][3], af0, B0.w, B1.w);
            mma_tf32(accf[1][3], af1, B0.w, B1.w);
        }
        pbuf ^= 1; va = na; vb = nb;

        // ---- per-ntile epilogue: screen + candidate push ----
        if (dchunk == 7) {
            #pragma unroll
            for (int mt = 0; mt < 2; mt++) {
                #pragma unroll
                for (int h = 0; h < 2; h++) {
                    int row = 32 * mg + 16 * mt + lr + 8 * h;
                    float A = An[row];
                    float dl[8]; float m = 3.4e38f;
                    #pragma unroll
                    for (int ns = 0; ns < 4; ns++)
                        #pragma unroll
                        for (int c = 0; c < 2; c++) {
                            int col = ntile * TILEN + ng * 32 + ns * 8 + 2 * lc + c;
                            float dv = A - 2.f * accf[mt][ns][2 * h + c] + Ns[col];
                            dl[ns * 2 + c] = dv;
                            m = fminf(m, dv);
                        }
                    float m2 = m;
                    m2 = fminf(m2, __shfl_xor_sync(0xffffffffu, m2, 1));
                    m2 = fminf(m2, __shfl_xor_sync(0xffffffffu, m2, 2));
                    float rm  = __uint_as_float(runmin[row]);   // racy = conservative
                    float thr = fminf(m2, rm) + WINDOW;
                    #pragma unroll
                    for (int e = 0; e < 8; e++) {
                        if (dl[e] <= thr) {
                            int col = ntile * TILEN + ng * 32 + (e >> 1) * 8
                                    + 2 * lc + (e & 1);
                            int slot = atomicAdd(&cnt[row], 1);
                            if (slot < CAP)
                                cand[row * CAP + slot] =
                                    (__float_as_uint(fmaxf(dl[e], 0.f)) & 0xFFFFFC00u)
                                    | (uint32_t)col;
                        }
                    }
                    if (lc == 0)
                        atomicMin(runmin + row, __float_as_uint(fmaxf(m2, 0.f)));
                }
            }
        }
    }
    __syncthreads();

    // ---- exact rescore, 4-way parallel per row (bit-identical chain) ----
    {
        int row = tid & 127, sl = tid >> 7;
        float thrF = __uint_as_float(runmin[row]) + WINDOW;
        int n = cnt[row]; if (n > CAP) n = CAP;
        float bv = 3.4e38f; int bi = 1 << 30;
        const float* ar = gA + (size_t)row * ND;
        float A = An[row];
        for (int s = sl; s < n; s += 4) {
            uint32_t u = cand[row * CAP + s];
            if (__uint_as_float(u & 0xFFFFFC00u) > thrF) continue;
            int col = (int)(u & 1023u);
            const float* wr = W + (size_t)col * ND;
            float acc = 0.f;
            #pragma unroll 8
            for (int d = 0; d < ND; d++) acc = __fmaf_rn(ar[d], wr[d], acc);
            float de = __fadd_rn(__fsub_rn(A, __fmul_rn(2.f, acc)), Ns[col]);
            if (de < bv || (de == bv && col < bi)) { bv = de; bi = col; }
        }
        pbv[row * 4 + sl] = bv;
        pbi[row * 4 + sl] = bi;
    }
    __syncthreads();
    if (tid < TM) {
        float bv = pbv[tid * 4]; int bi = pbi[tid * 4];
        #pragma unroll
        for (int t = 1; t < 4; t++) {
            float v = pbv[tid * 4 + t]; int ii = pbi[tid * 4 + t];
            if (v < bv || (v == bv && ii < bi)) { bv = v; bi = ii; }
        }
        if (bi >= NK) bi = 0;              // unreachable by construction
        RowIdx[tid] = bi;
        if (write_idx) {
            int nn = row0 + tid;
            int b = nn >> 11;              // T = 2048
            int t = nn & (NT - 1);
            idx_out[(size_t)b * NL * NT + (size_t)l * NT + t] = (float)bi;
        }
    }
    __syncthreads();

    // ---- residual -= gathered code ----
    {
        float4*       gout = (float4*)(g_res + (size_t)row0 * ND);
        const float4* gin  = (const float4*)gA;
        #pragma unroll
        for (int it = 0; it < (TM * (ND / 4)) / NTHREADS; it++) {
            int e   = tid + it * NTHREADS;
            int row = e >> 6;
            int d4  = e & 63;
            float4 w4 = *(const float4*)(W + (size_t)RowIdx[row] * ND + 4 * d4);
            float4 a4 = gin[e];
            gout[e] = make_float4(__fsub_rn(a4.x, w4.x), __fsub_rn(a4.y, w4.y),
                                  __fsub_rn(a4.z, w4.z), __fsub_rn(a4.w, w4.w));
        }
    }
}

// ---------------------------------------------------------------- launch
extern "C" void kernel_launch(void* const* d_in, const int* in_sizes, int n_in,
                              void* d_out, int out_size) {
    const float* x  = (const float*)d_in[0];
    const float* cb = (const float*)d_in[1];
    if (n_in >= 2 && in_sizes[0] == NL * NK * ND && in_sizes[1] == NB * ND * NT) {
        const float* t = x; x = cb; cb = t;
    }
    float* out = (float*)d_out;
    int write_idx = (out_size >= NOUT + NIDX) ? 1 : 0;

    cudaFuncSetAttribute(vq_layer_kernel,
                         cudaFuncAttributeMaxDynamicSharedMemorySize, SMEM_BYTES);

    norms_kernel<<<(NL * NK * 32 + 255) / 256, 256>>>(cb);

    dim3 tb(32, 8);
    tin_kernel<<<dim3(NT / 32, ND / 32, NB), tb>>>(x);

    for (int l = 0; l < NL; l++)
        vq_layer_kernel<<<NVEC / TM, NTHREADS, SMEM_BYTES>>>(cb, out + NOUT, l, write_idx);

    tout_kernel<<<dim3(NT / 32, ND / 32, NB), tb>>>(x, out);
}